// round 9
// baseline (speedup 1.0000x reference)
#include <cuda_runtime.h>
#include <cuda_bf16.h>

// ---------------------------------------------------------------------------
// GNN15: two GAT branches (int: 400K edges deg~4, nh: 1.6M edges deg~16)
// over 100K nodes, HEADS=3, FILT=16, then attention pooling to a scalar.
//
// R9: edge weights p precomputed in fill (edge-per-thread, 8x cheaper than
// in the octet consume loop); bucket entries are (p0,p1,p2,src) int4.
// Degree-binned row ordering so each warp's 4 octets have equal degree.
//   out[d] = (sum_e p_e * h[src_e]) / (den[d] + eps)  (normalize in pooling)
// ---------------------------------------------------------------------------

#define NN      100000
#define E_INT   400000
#define E_NH    1600000
#define VF      11
#define HEADS   3
#define HF      48
#define RS      64       // h/out row stride (floats) = 256B, 128B-aligned
#define XDIM    96
#define CAP0    32
#define CAP1    64
#define NBIN    98       // 33 bins (branch0 deg 0..32) + 65 (branch1 deg 0..64)
#define LOG2E   1.4426950408889634f

// ---------------- scratch (static device globals; no allocation) -----------
__device__ __align__(256) float g_h0[NN * RS];     // h[0..47] per row
__device__ __align__(256) float g_h1[NN * RS];
__device__ __align__(16) float4 g_es4_0[NN];       // es*log2e
__device__ __align__(16) float4 g_es4_1[NN];
__device__ __align__(16) float4 g_ed4_0[NN];       // ed*log2e
__device__ __align__(16) float4 g_ed4_1[NN];
__device__ __align__(256) float g_out0[NN * RS];   // raw sums, den @ slot12
__device__ __align__(256) float g_out1[NN * RS];
__device__ int g_cnt0[NN];                          // zero-init; self-resetting
__device__ int g_cnt1[NN];
__device__ __align__(16) int4 g_ent0[NN * CAP0];    // (p0,p1,p2 bits, src)
__device__ __align__(16) int4 g_ent1[NN * CAP1];
__device__ int g_bincnt[NBIN];
__device__ int g_bincur[NBIN];
__device__ int g_order[2 * NN];                     // degree-sorted row ids
__device__ float g_acc[8];                          // num[3], den[3]; self-reset
__device__ int   g_is64[2];

__device__ __forceinline__ float ex2(float x) {
    float r;
    asm("ex2.approx.f32 %0, %1;" : "=f"(r) : "f"(x));
    return r;
}

// ---------------- detect edge dtype + zero bins -----------------------------
// jax "int64" edges are int32 unless x64 is enabled. Values < 1e5 << 2^31,
// so if truly int64 every odd int32 word is 0. Check 16 of them.
__global__ void detect_kernel(const void* e0, const void* e1) {
    int t = threadIdx.x;
    if (t < NBIN) g_bincnt[t] = 0;
    if (t == 0) {
        const int* a = (const int*)e0;
        const int* b = (const int*)e1;
        int is64a = 1, is64b = 1;
        #pragma unroll
        for (int k = 0; k < 16; k++) {
            if (a[2 * k + 1] != 0) is64a = 0;
            if (b[2 * k + 1] != 0) is64b = 0;
        }
        g_is64[0] = is64a;
        g_is64[1] = is64b;
    }
}

// ---------------- node transform -------------------------------------------
__global__ void node_kernel(const float* __restrict__ feats,
                            const float* __restrict__ W0,
                            const float* __restrict__ as0, const float* __restrict__ ad0,
                            const float* __restrict__ W1,
                            const float* __restrict__ as1, const float* __restrict__ ad1) {
    __shared__ float sW[2][VF * HF];
    __shared__ float sAs[2][HF];
    __shared__ float sAd[2][HF];
    int tid = threadIdx.x;
    for (int i = tid; i < VF * HF; i += blockDim.x) { sW[0][i] = W0[i]; sW[1][i] = W1[i]; }
    for (int i = tid; i < HF; i += blockDim.x) {
        sAs[0][i] = as0[i]; sAd[0][i] = ad0[i];
        sAs[1][i] = as1[i]; sAd[1][i] = ad1[i];
    }
    __syncthreads();

    int n = blockIdx.x * blockDim.x + tid;
    if (n >= NN) return;

    float x[VF];
    #pragma unroll
    for (int k = 0; k < VF; k++) x[k] = feats[(size_t)n * VF + k];

    #pragma unroll
    for (int b = 0; b < 2; b++) {
        float* hout = (b == 0 ? g_h0 : g_h1) + (size_t)n * RS;
        float es[HEADS] = {0.f, 0.f, 0.f};
        float ed[HEADS] = {0.f, 0.f, 0.f};
        #pragma unroll
        for (int j = 0; j < HF; j++) {
            float s = 0.f;
            #pragma unroll
            for (int k = 0; k < VF; k++) s += x[k] * sW[b][k * HF + j];
            hout[j] = s;
            int hh = j >> 4;
            es[hh] += s * sAs[b][j];
            ed[hh] += s * sAd[b][j];
        }
        // log2e folded in: lrelu is positively homogeneous, so
        // exp(lrelu(v)) = ex2(lrelu(v*log2e)) exactly.
        (b == 0 ? g_es4_0 : g_es4_1)[n] =
            make_float4(es[0] * LOG2E, es[1] * LOG2E, es[2] * LOG2E, 0.f);
        (b == 0 ? g_ed4_0 : g_ed4_1)[n] =
            make_float4(ed[0] * LOG2E, ed[1] * LOG2E, ed[2] * LOG2E, 0.f);
    }
}

// ---------------- fill: bucketed CSR build with precomputed p --------------
__device__ __forceinline__ void fill_one(int s, int d,
                                         const float4* __restrict__ es4,
                                         const float4* __restrict__ ed4,
                                         int* __restrict__ cnt,
                                         int4* __restrict__ ent, int cap) {
    float4 a = es4[s];
    float4 b = ed4[d];
    float v0 = a.x + b.x, v1 = a.y + b.y, v2 = a.z + b.z;
    v0 = v0 > 0.f ? v0 : 0.2f * v0;            // leaky_relu(0.2), log2-domain
    v1 = v1 > 0.f ? v1 : 0.2f * v1;
    v2 = v2 > 0.f ? v2 : 0.2f * v2;
    float p0 = ex2(v0), p1 = ex2(v1), p2 = ex2(v2);
    int pos = atomicAdd(&cnt[d], 1);
    if (pos < cap)
        ent[d * cap + pos] = make_int4(__float_as_int(p0), __float_as_int(p1),
                                       __float_as_int(p2), s);
}

__global__ void fill_kernel(const void* __restrict__ e0, const void* __restrict__ e1) {
    int t = blockIdx.x * blockDim.x + threadIdx.x;
    const int H0 = E_INT / 2, H1 = E_NH / 2;
    if (t < H0) {
        int s0, s1, d0, d1;
        if (g_is64[0]) {
            const longlong2* p = (const longlong2*)e0;
            longlong2 sv = p[t], dv = p[H0 + t];
            s0 = (int)sv.x; s1 = (int)sv.y; d0 = (int)dv.x; d1 = (int)dv.y;
        } else {
            const int2* p = (const int2*)e0;
            int2 sv = p[t], dv = p[H0 + t];
            s0 = sv.x; s1 = sv.y; d0 = dv.x; d1 = dv.y;
        }
        fill_one(s0, d0, g_es4_0, g_ed4_0, g_cnt0, g_ent0, CAP0);
        fill_one(s1, d1, g_es4_0, g_ed4_0, g_cnt0, g_ent0, CAP0);
    } else if (t < H0 + H1) {
        int u = t - H0;
        int s0, s1, d0, d1;
        if (g_is64[1]) {
            const longlong2* p = (const longlong2*)e1;
            longlong2 sv = p[u], dv = p[H1 + u];
            s0 = (int)sv.x; s1 = (int)sv.y; d0 = (int)dv.x; d1 = (int)dv.y;
        } else {
            const int2* p = (const int2*)e1;
            int2 sv = p[u], dv = p[H1 + u];
            s0 = sv.x; s1 = sv.y; d0 = dv.x; d1 = dv.y;
        }
        fill_one(s0, d0, g_es4_1, g_ed4_1, g_cnt1, g_ent1, CAP1);
        fill_one(s1, d1, g_es4_1, g_ed4_1, g_cnt1, g_ent1, CAP1);
    }
}

// ---------------- degree binning: count -> scan -> scatter -----------------
__global__ void binA_kernel() {
    int i = blockIdx.x * blockDim.x + threadIdx.x;
    if (i >= 2 * NN) return;
    int bin;
    if (i < NN) {
        int deg = g_cnt0[i]; deg = deg < CAP0 ? deg : CAP0;
        bin = deg;
    } else {
        int deg = g_cnt1[i - NN]; deg = deg < CAP1 ? deg : CAP1;
        bin = 33 + deg;
    }
    atomicAdd(&g_bincnt[bin], 1);
}

__global__ void binB_kernel() {
    if (threadIdx.x == 0) {
        int run = 0;
        for (int b = 0; b < NBIN; b++) { g_bincur[b] = run; run += g_bincnt[b]; }
    }
}

__global__ void binC_kernel() {
    int i = blockIdx.x * blockDim.x + threadIdx.x;
    if (i >= 2 * NN) return;
    int bin;
    if (i < NN) {
        int deg = g_cnt0[i]; deg = deg < CAP0 ? deg : CAP0;
        bin = deg;
    } else {
        int deg = g_cnt1[i - NN]; deg = deg < CAP1 ? deg : CAP1;
        bin = 33 + deg;
    }
    int pos = atomicAdd(&g_bincur[bin], 1);
    g_order[pos] = i;
}

// ---------------- consume: octet per dst row, p from bucket entries --------
__device__ __forceinline__ void edge_acc(int4 E, float4 hA, float4 hB, int sub,
                                         float4& acc0, float4& acc1,
                                         float& d0, float& d1, float& d2) {
    float p0 = __int_as_float(E.x);
    float p1 = __int_as_float(E.y);
    float p2 = __int_as_float(E.z);
    float pa = sub < 4 ? p0 : p1;
    acc0.x += pa * hA.x; acc0.y += pa * hA.y;
    acc0.z += pa * hA.z; acc0.w += pa * hA.w;
    acc1.x += p2 * hB.x; acc1.y += p2 * hB.y;   // lanes 4-7: unused result
    acc1.z += p2 * hB.z; acc1.w += p2 * hB.w;
    d0 += p0; d1 += p1; d2 += p2;
}

__global__ void __launch_bounds__(256, 4) consume_kernel() {
    int t = blockIdx.x * blockDim.x + threadIdx.x;
    int oc = t >> 3, sub = t & 7;
    if (oc >= 2 * NN) return;
    int v = g_order[oc];

    const float* h;
    const int4* ent;
    float* orow;
    int* cntp;
    if (v < NN) {
        int r = v;
        h = g_h0; ent = g_ent0 + (size_t)r * CAP0;
        orow = g_out0 + (size_t)r * RS;
        cntp = &g_cnt0[r];
        int deg = *cntp; deg = deg < CAP0 ? deg : CAP0;
        v = deg;                         // reuse v as deg below
    } else {
        int r = v - NN;
        h = g_h1; ent = g_ent1 + (size_t)r * CAP1;
        orow = g_out1 + (size_t)r * RS;
        cntp = &g_cnt1[r];
        int deg = *cntp; deg = deg < CAP1 ? deg : CAP1;
        v = deg;
    }
    int deg = v;
    int subm = 8 + (sub & 3);            // head2 slots 8..11 (lanes 4-7 dup)

    float4 acc0 = make_float4(0.f, 0.f, 0.f, 0.f);
    float4 acc1 = make_float4(0.f, 0.f, 0.f, 0.f);
    float d0 = 0.f, d1 = 0.f, d2 = 0.f;

    int i = 0;
    for (; i + 4 <= deg; i += 4) {
        int4 E0 = ent[i], E1 = ent[i + 1], E2 = ent[i + 2], E3 = ent[i + 3];
        const float4* r0 = (const float4*)(h + (size_t)E0.w * RS);
        const float4* r1 = (const float4*)(h + (size_t)E1.w * RS);
        const float4* r2 = (const float4*)(h + (size_t)E2.w * RS);
        const float4* r3 = (const float4*)(h + (size_t)E3.w * RS);
        float4 A0 = r0[sub], B0 = r0[subm];
        float4 A1 = r1[sub], B1 = r1[subm];
        float4 A2 = r2[sub], B2 = r2[subm];
        float4 A3 = r3[sub], B3 = r3[subm];
        edge_acc(E0, A0, B0, sub, acc0, acc1, d0, d1, d2);
        edge_acc(E1, A1, B1, sub, acc0, acc1, d0, d1, d2);
        edge_acc(E2, A2, B2, sub, acc0, acc1, d0, d1, d2);
        edge_acc(E3, A3, B3, sub, acc0, acc1, d0, d1, d2);
    }
    for (; i < deg; i++) {
        int4 E = ent[i];
        const float4* hr = (const float4*)(h + (size_t)E.w * RS);
        float4 hA = hr[sub];
        float4 hB = hr[subm];
        edge_acc(E, hA, hB, sub, acc0, acc1, d0, d1, d2);
    }

    float4* or4 = (float4*)orow;
    or4[sub] = acc0;                                       // heads 0,1
    if (sub < 4) or4[8 + sub] = acc1;                      // head 2
    if (sub == 4) or4[12] = make_float4(d0, d1, d2, 0.f);  // den @ slot 12
    if (sub == 5) *cntp = 0;                               // reset for next replay
}

// ---------------- pooling: normalize + fused tanh-attention reduction ------
// x_n[d] = raw[n][d] / (den[n][head(d)] + 1e-16)
// out = sum_h ( sum_n e^{tanh(x_n . attw_h)} * (x_n . dw_h) )
//             / ( sum_n e^{tanh(x_n . attw_h)} )  + b
__global__ void pool_kernel(const float* __restrict__ attw,
                            const float* __restrict__ dw) {
    __shared__ float sA[XDIM * HEADS];   // attw: [96,3] row-major
    __shared__ float sD[XDIM * HEADS];   // dense_w: [288] = [3][96] h-major
    int tid = threadIdx.x;
    for (int i = tid; i < XDIM * HEADS; i += blockDim.x) { sA[i] = attw[i]; sD[i] = dw[i]; }
    __syncthreads();

    int n = blockIdx.x * blockDim.x + tid;
    float sh[HEADS] = {0.f, 0.f, 0.f};
    float dh[HEADS] = {0.f, 0.f, 0.f};
    if (n < NN) {
        const float4* x0 = (const float4*)(g_out0 + (size_t)n * RS);
        const float4* x1 = (const float4*)(g_out1 + (size_t)n * RS);
        float4 dn0 = x0[12];
        float4 dn1 = x1[12];
        float inv0[HEADS] = {1.f / (dn0.x + 1e-16f), 1.f / (dn0.y + 1e-16f), 1.f / (dn0.z + 1e-16f)};
        float inv1[HEADS] = {1.f / (dn1.x + 1e-16f), 1.f / (dn1.y + 1e-16f), 1.f / (dn1.z + 1e-16f)};
        #pragma unroll
        for (int j = 0; j < HF / 4; j++) {
            float4 v0 = x0[j];
            float4 v1 = x1[j];
            int hh = j >> 2;
            float q0[4] = {v0.x * inv0[hh], v0.y * inv0[hh], v0.z * inv0[hh], v0.w * inv0[hh]};
            float q1[4] = {v1.x * inv1[hh], v1.y * inv1[hh], v1.z * inv1[hh], v1.w * inv1[hh]};
            #pragma unroll
            for (int c = 0; c < 4; c++) {
                int dA = j * 4 + c;
                int dB = dA + HF;
                #pragma unroll
                for (int h = 0; h < HEADS; h++) {
                    sh[h] += q0[c] * sA[dA * HEADS + h] + q1[c] * sA[dB * HEADS + h];
                    dh[h] += q0[c] * sD[h * XDIM + dA] + q1[c] * sD[h * XDIM + dB];
                }
            }
        }
    }
    float num[HEADS], den[HEADS];
    #pragma unroll
    for (int h = 0; h < HEADS; h++) {
        float w = (n < NN) ? __expf(tanhf(sh[h])) : 0.f;
        num[h] = w * dh[h];
        den[h] = w;
    }
    #pragma unroll
    for (int off = 16; off > 0; off >>= 1) {
        #pragma unroll
        for (int h = 0; h < HEADS; h++) {
            num[h] += __shfl_down_sync(0xFFFFFFFFu, num[h], off);
            den[h] += __shfl_down_sync(0xFFFFFFFFu, den[h], off);
        }
    }
    if ((tid & 31) == 0) {
        #pragma unroll
        for (int h = 0; h < HEADS; h++) {
            atomicAdd(&g_acc[h], num[h]);
            atomicAdd(&g_acc[HEADS + h], den[h]);
        }
    }
}

__global__ void finalize_kernel(const float* __restrict__ bias, float* __restrict__ out) {
    float r = 0.f;
    #pragma unroll
    for (int h = 0; h < HEADS; h++) r += g_acc[h] / g_acc[HEADS + h];
    out[0] = r + bias[0];
    #pragma unroll
    for (int t = 0; t < 8; t++) g_acc[t] = 0.f;    // reset for next replay
}

// ---------------------------------------------------------------------------
extern "C" void kernel_launch(void* const* d_in, const int* in_sizes, int n_in,
                              void* d_out, int out_size) {
    const float* node_feats = (const float*)d_in[0];
    const float* W_int   = (const float*)d_in[1];
    const float* asrc_i  = (const float*)d_in[2];
    const float* adst_i  = (const float*)d_in[3];
    const float* W_nh    = (const float*)d_in[4];
    const float* asrc_n  = (const float*)d_in[5];
    const float* adst_n  = (const float*)d_in[6];
    const float* att_w   = (const float*)d_in[7];
    const float* dense_w = (const float*)d_in[8];
    const float* dense_b = (const float*)d_in[9];
    const void*  edge_i  = d_in[10];
    const void*  edge_n  = d_in[11];
    float* out = (float*)d_out;

    detect_kernel<<<1, 128>>>(edge_i, edge_n);
    node_kernel<<<(NN + 255) / 256, 256>>>(node_feats, W_int, asrc_i, adst_i,
                                           W_nh, asrc_n, adst_n);
    fill_kernel<<<((E_INT + E_NH) / 2 + 255) / 256, 256>>>(edge_i, edge_n);
    binA_kernel<<<(2 * NN + 255) / 256, 256>>>();
    binB_kernel<<<1, 32>>>();
    binC_kernel<<<(2 * NN + 255) / 256, 256>>>();
    consume_kernel<<<(2 * NN * 8 + 255) / 256, 256>>>();
    pool_kernel<<<(NN + 255) / 256, 256>>>(att_w, dense_w);
    finalize_kernel<<<1, 1>>>(dense_b, out);
}

// round 10
// speedup vs baseline: 1.4326x; 1.4326x over previous
#include <cuda_runtime.h>
#include <cuda_bf16.h>

// ---------------------------------------------------------------------------
// GNN15: two GAT branches (int: 400K edges deg~4, nh: 1.6M edges deg~16)
// over 100K nodes, HEADS=3, FILT=16, then attention pooling to a scalar.
//
// R10: R9 (edge weights p precomputed in fill; bucket entries (p0,p1,p2,src))
// WITHOUT the degree-binning kernels — their 98-address global atomics
// serialized in L2 and cost ~90us. Consume walks rows in natural order.
//   out[d] = (sum_e p_e * h[src_e]) / (den[d] + eps)  (normalize in pooling)
// ---------------------------------------------------------------------------

#define NN      100000
#define E_INT   400000
#define E_NH    1600000
#define VF      11
#define HEADS   3
#define HF      48
#define RS      64       // h/out row stride (floats) = 256B, 128B-aligned
#define XDIM    96
#define CAP0    32
#define CAP1    64
#define LOG2E   1.4426950408889634f

// ---------------- scratch (static device globals; no allocation) -----------
__device__ __align__(256) float g_h0[NN * RS];     // h[0..47] per row
__device__ __align__(256) float g_h1[NN * RS];
__device__ __align__(16) float4 g_es4_0[NN];       // es*log2e
__device__ __align__(16) float4 g_es4_1[NN];
__device__ __align__(16) float4 g_ed4_0[NN];       // ed*log2e
__device__ __align__(16) float4 g_ed4_1[NN];
__device__ __align__(256) float g_out0[NN * RS];   // raw sums, den @ slot12
__device__ __align__(256) float g_out1[NN * RS];
__device__ int g_cnt0[NN];                          // zero-init; self-resetting
__device__ int g_cnt1[NN];
__device__ __align__(16) int4 g_ent0[NN * CAP0];    // (p0,p1,p2 bits, src)
__device__ __align__(16) int4 g_ent1[NN * CAP1];
__device__ float g_acc[8];                          // num[3], den[3]; self-reset
__device__ int   g_is64[2];

__device__ __forceinline__ float ex2(float x) {
    float r;
    asm("ex2.approx.f32 %0, %1;" : "=f"(r) : "f"(x));
    return r;
}

// ---------------- detect edge dtype ----------------------------------------
// jax "int64" edges are int32 unless x64 is enabled. Values < 1e5 << 2^31,
// so if truly int64 every odd int32 word is 0. Check 16 of them.
__global__ void detect_kernel(const void* e0, const void* e1) {
    if (threadIdx.x == 0) {
        const int* a = (const int*)e0;
        const int* b = (const int*)e1;
        int is64a = 1, is64b = 1;
        #pragma unroll
        for (int k = 0; k < 16; k++) {
            if (a[2 * k + 1] != 0) is64a = 0;
            if (b[2 * k + 1] != 0) is64b = 0;
        }
        g_is64[0] = is64a;
        g_is64[1] = is64b;
    }
}

// ---------------- node transform -------------------------------------------
__global__ void node_kernel(const float* __restrict__ feats,
                            const float* __restrict__ W0,
                            const float* __restrict__ as0, const float* __restrict__ ad0,
                            const float* __restrict__ W1,
                            const float* __restrict__ as1, const float* __restrict__ ad1) {
    __shared__ float sW[2][VF * HF];
    __shared__ float sAs[2][HF];
    __shared__ float sAd[2][HF];
    int tid = threadIdx.x;
    for (int i = tid; i < VF * HF; i += blockDim.x) { sW[0][i] = W0[i]; sW[1][i] = W1[i]; }
    for (int i = tid; i < HF; i += blockDim.x) {
        sAs[0][i] = as0[i]; sAd[0][i] = ad0[i];
        sAs[1][i] = as1[i]; sAd[1][i] = ad1[i];
    }
    __syncthreads();

    int n = blockIdx.x * blockDim.x + tid;
    if (n >= NN) return;

    float x[VF];
    #pragma unroll
    for (int k = 0; k < VF; k++) x[k] = feats[(size_t)n * VF + k];

    #pragma unroll
    for (int b = 0; b < 2; b++) {
        float* hout = (b == 0 ? g_h0 : g_h1) + (size_t)n * RS;
        float es[HEADS] = {0.f, 0.f, 0.f};
        float ed[HEADS] = {0.f, 0.f, 0.f};
        #pragma unroll
        for (int j = 0; j < HF; j++) {
            float s = 0.f;
            #pragma unroll
            for (int k = 0; k < VF; k++) s += x[k] * sW[b][k * HF + j];
            hout[j] = s;
            int hh = j >> 4;
            es[hh] += s * sAs[b][j];
            ed[hh] += s * sAd[b][j];
        }
        // log2e folded in: lrelu is positively homogeneous, so
        // exp(lrelu(v)) = ex2(lrelu(v*log2e)) exactly.
        (b == 0 ? g_es4_0 : g_es4_1)[n] =
            make_float4(es[0] * LOG2E, es[1] * LOG2E, es[2] * LOG2E, 0.f);
        (b == 0 ? g_ed4_0 : g_ed4_1)[n] =
            make_float4(ed[0] * LOG2E, ed[1] * LOG2E, ed[2] * LOG2E, 0.f);
    }
}

// ---------------- fill: bucketed CSR build with precomputed p --------------
__device__ __forceinline__ void fill_one(int s, int d,
                                         const float4* __restrict__ es4,
                                         const float4* __restrict__ ed4,
                                         int* __restrict__ cnt,
                                         int4* __restrict__ ent, int cap) {
    float4 a = es4[s];
    float4 b = ed4[d];
    float v0 = a.x + b.x, v1 = a.y + b.y, v2 = a.z + b.z;
    v0 = v0 > 0.f ? v0 : 0.2f * v0;            // leaky_relu(0.2), log2-domain
    v1 = v1 > 0.f ? v1 : 0.2f * v1;
    v2 = v2 > 0.f ? v2 : 0.2f * v2;
    float p0 = ex2(v0), p1 = ex2(v1), p2 = ex2(v2);
    int pos = atomicAdd(&cnt[d], 1);
    if (pos < cap)
        ent[d * cap + pos] = make_int4(__float_as_int(p0), __float_as_int(p1),
                                       __float_as_int(p2), s);
}

__global__ void fill_kernel(const void* __restrict__ e0, const void* __restrict__ e1) {
    int t = blockIdx.x * blockDim.x + threadIdx.x;
    const int H0 = E_INT / 2, H1 = E_NH / 2;
    if (t < H0) {
        int s0, s1, d0, d1;
        if (g_is64[0]) {
            const longlong2* p = (const longlong2*)e0;
            longlong2 sv = p[t], dv = p[H0 + t];
            s0 = (int)sv.x; s1 = (int)sv.y; d0 = (int)dv.x; d1 = (int)dv.y;
        } else {
            const int2* p = (const int2*)e0;
            int2 sv = p[t], dv = p[H0 + t];
            s0 = sv.x; s1 = sv.y; d0 = dv.x; d1 = dv.y;
        }
        fill_one(s0, d0, g_es4_0, g_ed4_0, g_cnt0, g_ent0, CAP0);
        fill_one(s1, d1, g_es4_0, g_ed4_0, g_cnt0, g_ent0, CAP0);
    } else if (t < H0 + H1) {
        int u = t - H0;
        int s0, s1, d0, d1;
        if (g_is64[1]) {
            const longlong2* p = (const longlong2*)e1;
            longlong2 sv = p[u], dv = p[H1 + u];
            s0 = (int)sv.x; s1 = (int)sv.y; d0 = (int)dv.x; d1 = (int)dv.y;
        } else {
            const int2* p = (const int2*)e1;
            int2 sv = p[u], dv = p[H1 + u];
            s0 = sv.x; s1 = sv.y; d0 = dv.x; d1 = dv.y;
        }
        fill_one(s0, d0, g_es4_1, g_ed4_1, g_cnt1, g_ent1, CAP1);
        fill_one(s1, d1, g_es4_1, g_ed4_1, g_cnt1, g_ent1, CAP1);
    }
}

// ---------------- consume: octet per dst row, p from bucket entries --------
__device__ __forceinline__ void edge_acc(int4 E, float4 hA, float4 hB, int sub,
                                         float4& acc0, float4& acc1,
                                         float& d0, float& d1, float& d2) {
    float p0 = __int_as_float(E.x);
    float p1 = __int_as_float(E.y);
    float p2 = __int_as_float(E.z);
    float pa = sub < 4 ? p0 : p1;
    acc0.x += pa * hA.x; acc0.y += pa * hA.y;
    acc0.z += pa * hA.z; acc0.w += pa * hA.w;
    acc1.x += p2 * hB.x; acc1.y += p2 * hB.y;   // lanes 4-7: unused result
    acc1.z += p2 * hB.z; acc1.w += p2 * hB.w;
    d0 += p0; d1 += p1; d2 += p2;
}

__global__ void __launch_bounds__(256, 4) consume_kernel() {
    int t = blockIdx.x * blockDim.x + threadIdx.x;
    int oc = t >> 3, sub = t & 7;
    if (oc >= 2 * NN) return;

    const float* h;
    const int4* ent;
    float* orow;
    int* cntp;
    int cap;
    if (oc < NN) {
        int r = oc;
        h = g_h0; ent = g_ent0 + (size_t)r * CAP0;
        orow = g_out0 + (size_t)r * RS;
        cntp = &g_cnt0[r]; cap = CAP0;
    } else {
        int r = oc - NN;
        h = g_h1; ent = g_ent1 + (size_t)r * CAP1;
        orow = g_out1 + (size_t)r * RS;
        cntp = &g_cnt1[r]; cap = CAP1;
    }
    int deg = *cntp;
    deg = deg < cap ? deg : cap;
    int subm = 8 + (sub & 3);            // head2 slots 8..11 (lanes 4-7 dup)

    float4 acc0 = make_float4(0.f, 0.f, 0.f, 0.f);
    float4 acc1 = make_float4(0.f, 0.f, 0.f, 0.f);
    float d0 = 0.f, d1 = 0.f, d2 = 0.f;

    int i = 0;
    for (; i + 4 <= deg; i += 4) {
        int4 E0 = ent[i], E1 = ent[i + 1], E2 = ent[i + 2], E3 = ent[i + 3];
        const float4* r0 = (const float4*)(h + (size_t)E0.w * RS);
        const float4* r1 = (const float4*)(h + (size_t)E1.w * RS);
        const float4* r2 = (const float4*)(h + (size_t)E2.w * RS);
        const float4* r3 = (const float4*)(h + (size_t)E3.w * RS);
        float4 A0 = r0[sub], B0 = r0[subm];
        float4 A1 = r1[sub], B1 = r1[subm];
        float4 A2 = r2[sub], B2 = r2[subm];
        float4 A3 = r3[sub], B3 = r3[subm];
        edge_acc(E0, A0, B0, sub, acc0, acc1, d0, d1, d2);
        edge_acc(E1, A1, B1, sub, acc0, acc1, d0, d1, d2);
        edge_acc(E2, A2, B2, sub, acc0, acc1, d0, d1, d2);
        edge_acc(E3, A3, B3, sub, acc0, acc1, d0, d1, d2);
    }
    for (; i < deg; i++) {
        int4 E = ent[i];
        const float4* hr = (const float4*)(h + (size_t)E.w * RS);
        float4 hA = hr[sub];
        float4 hB = hr[subm];
        edge_acc(E, hA, hB, sub, acc0, acc1, d0, d1, d2);
    }

    float4* or4 = (float4*)orow;
    or4[sub] = acc0;                                       // heads 0,1
    if (sub < 4) or4[8 + sub] = acc1;                      // head 2
    if (sub == 4) or4[12] = make_float4(d0, d1, d2, 0.f);  // den @ slot 12
    if (sub == 5) *cntp = 0;                               // reset for next replay
}

// ---------------- pooling: normalize + fused tanh-attention reduction ------
// x_n[d] = raw[n][d] / (den[n][head(d)] + 1e-16)
// out = sum_h ( sum_n e^{tanh(x_n . attw_h)} * (x_n . dw_h) )
//             / ( sum_n e^{tanh(x_n . attw_h)} )  + b
__global__ void pool_kernel(const float* __restrict__ attw,
                            const float* __restrict__ dw) {
    __shared__ float sA[XDIM * HEADS];   // attw: [96,3] row-major
    __shared__ float sD[XDIM * HEADS];   // dense_w: [288] = [3][96] h-major
    int tid = threadIdx.x;
    for (int i = tid; i < XDIM * HEADS; i += blockDim.x) { sA[i] = attw[i]; sD[i] = dw[i]; }
    __syncthreads();

    int n = blockIdx.x * blockDim.x + tid;
    float sh[HEADS] = {0.f, 0.f, 0.f};
    float dh[HEADS] = {0.f, 0.f, 0.f};
    if (n < NN) {
        const float4* x0 = (const float4*)(g_out0 + (size_t)n * RS);
        const float4* x1 = (const float4*)(g_out1 + (size_t)n * RS);
        float4 dn0 = x0[12];
        float4 dn1 = x1[12];
        float inv0[HEADS] = {1.f / (dn0.x + 1e-16f), 1.f / (dn0.y + 1e-16f), 1.f / (dn0.z + 1e-16f)};
        float inv1[HEADS] = {1.f / (dn1.x + 1e-16f), 1.f / (dn1.y + 1e-16f), 1.f / (dn1.z + 1e-16f)};
        #pragma unroll
        for (int j = 0; j < HF / 4; j++) {
            float4 v0 = x0[j];
            float4 v1 = x1[j];
            int hh = j >> 2;
            float q0[4] = {v0.x * inv0[hh], v0.y * inv0[hh], v0.z * inv0[hh], v0.w * inv0[hh]};
            float q1[4] = {v1.x * inv1[hh], v1.y * inv1[hh], v1.z * inv1[hh], v1.w * inv1[hh]};
            #pragma unroll
            for (int c = 0; c < 4; c++) {
                int dA = j * 4 + c;
                int dB = dA + HF;
                #pragma unroll
                for (int h = 0; h < HEADS; h++) {
                    sh[h] += q0[c] * sA[dA * HEADS + h] + q1[c] * sA[dB * HEADS + h];
                    dh[h] += q0[c] * sD[h * XDIM + dA] + q1[c] * sD[h * XDIM + dB];
                }
            }
        }
    }
    float num[HEADS], den[HEADS];
    #pragma unroll
    for (int h = 0; h < HEADS; h++) {
        float w = (n < NN) ? __expf(tanhf(sh[h])) : 0.f;
        num[h] = w * dh[h];
        den[h] = w;
    }
    #pragma unroll
    for (int off = 16; off > 0; off >>= 1) {
        #pragma unroll
        for (int h = 0; h < HEADS; h++) {
            num[h] += __shfl_down_sync(0xFFFFFFFFu, num[h], off);
            den[h] += __shfl_down_sync(0xFFFFFFFFu, den[h], off);
        }
    }
    if ((tid & 31) == 0) {
        #pragma unroll
        for (int h = 0; h < HEADS; h++) {
            atomicAdd(&g_acc[h], num[h]);
            atomicAdd(&g_acc[HEADS + h], den[h]);
        }
    }
}

__global__ void finalize_kernel(const float* __restrict__ bias, float* __restrict__ out) {
    float r = 0.f;
    #pragma unroll
    for (int h = 0; h < HEADS; h++) r += g_acc[h] / g_acc[HEADS + h];
    out[0] = r + bias[0];
    #pragma unroll
    for (int t = 0; t < 8; t++) g_acc[t] = 0.f;    // reset for next replay
}

// ---------------------------------------------------------------------------
extern "C" void kernel_launch(void* const* d_in, const int* in_sizes, int n_in,
                              void* d_out, int out_size) {
    const float* node_feats = (const float*)d_in[0];
    const float* W_int   = (const float*)d_in[1];
    const float* asrc_i  = (const float*)d_in[2];
    const float* adst_i  = (const float*)d_in[3];
    const float* W_nh    = (const float*)d_in[4];
    const float* asrc_n  = (const float*)d_in[5];
    const float* adst_n  = (const float*)d_in[6];
    const float* att_w   = (const float*)d_in[7];
    const float* dense_w = (const float*)d_in[8];
    const float* dense_b = (const float*)d_in[9];
    const void*  edge_i  = d_in[10];
    const void*  edge_n  = d_in[11];
    float* out = (float*)d_out;

    detect_kernel<<<1, 32>>>(edge_i, edge_n);
    node_kernel<<<(NN + 255) / 256, 256>>>(node_feats, W_int, asrc_i, adst_i,
                                           W_nh, asrc_n, adst_n);
    fill_kernel<<<((E_INT + E_NH) / 2 + 255) / 256, 256>>>(edge_i, edge_n);
    consume_kernel<<<(2 * NN * 8 + 255) / 256, 256>>>();
    pool_kernel<<<(NN + 255) / 256, 256>>>(att_w, dense_w);
    finalize_kernel<<<1, 1>>>(dense_b, out);
}

// round 11
// speedup vs baseline: 1.5532x; 1.0841x over previous
#include <cuda_runtime.h>
#include <cuda_bf16.h>

// ---------------------------------------------------------------------------
// GNN15: two GAT branches (int: 400K edges deg~4, nh: 1.6M edges deg~16)
// over 100K nodes, HEADS=3, FILT=16, then attention pooling to a scalar.
//
// R11: R10 core (fill precomputes p; octet-per-row gather consume) +
//  - pool rewritten octet-per-row (coalesced 2-line row reads, ~6x fewer wf)
//  - finalize fused into pool (last-block pattern), detect fused into node
//   out[d] = (sum_e p_e * h[src_e]) / (den[d] + eps)  (normalize in pooling)
// ---------------------------------------------------------------------------

#define NN      100000
#define E_INT   400000
#define E_NH    1600000
#define VF      11
#define HEADS   3
#define HF      48
#define RS      64       // h/out row stride (floats) = 256B, 128B-aligned
#define XDIM    96
#define CAP0    32
#define CAP1    64
#define LOG2E   1.4426950408889634f

// ---------------- scratch (static device globals; no allocation) -----------
__device__ __align__(256) float g_h0[NN * RS];     // h[0..47] per row
__device__ __align__(256) float g_h1[NN * RS];
__device__ __align__(16) float4 g_es4_0[NN];       // es*log2e
__device__ __align__(16) float4 g_es4_1[NN];
__device__ __align__(16) float4 g_ed4_0[NN];       // ed*log2e
__device__ __align__(16) float4 g_ed4_1[NN];
__device__ __align__(256) float g_out0[NN * RS];   // raw sums, den @ slot12
__device__ __align__(256) float g_out1[NN * RS];
__device__ int g_cnt0[NN];                          // zero-init; self-resetting
__device__ int g_cnt1[NN];
__device__ __align__(16) int4 g_ent0[NN * CAP0];    // (p0,p1,p2 bits, src)
__device__ __align__(16) int4 g_ent1[NN * CAP1];
__device__ float g_acc[8];                          // num[3], den[3]; self-reset
__device__ int   g_done;                            // pool last-block counter
__device__ int   g_is64[2];

__device__ __forceinline__ float ex2(float x) {
    float r;
    asm("ex2.approx.f32 %0, %1;" : "=f"(r) : "f"(x));
    return r;
}

// ---------------- node transform (+ edge dtype detect in block 0) ----------
// jax "int64" edges are int32 unless x64 is enabled. Values < 1e5 << 2^31,
// so if truly int64 every odd int32 word is 0. Check 16 of them.
__global__ void node_kernel(const float* __restrict__ feats,
                            const float* __restrict__ W0,
                            const float* __restrict__ as0, const float* __restrict__ ad0,
                            const float* __restrict__ W1,
                            const float* __restrict__ as1, const float* __restrict__ ad1,
                            const void* e0, const void* e1) {
    __shared__ float sW[2][VF * HF];
    __shared__ float sAs[2][HF];
    __shared__ float sAd[2][HF];
    int tid = threadIdx.x;
    if (blockIdx.x == 0 && tid == 0) {
        const int* a = (const int*)e0;
        const int* b = (const int*)e1;
        int is64a = 1, is64b = 1;
        #pragma unroll
        for (int k = 0; k < 16; k++) {
            if (a[2 * k + 1] != 0) is64a = 0;
            if (b[2 * k + 1] != 0) is64b = 0;
        }
        g_is64[0] = is64a;
        g_is64[1] = is64b;
    }
    for (int i = tid; i < VF * HF; i += blockDim.x) { sW[0][i] = W0[i]; sW[1][i] = W1[i]; }
    for (int i = tid; i < HF; i += blockDim.x) {
        sAs[0][i] = as0[i]; sAd[0][i] = ad0[i];
        sAs[1][i] = as1[i]; sAd[1][i] = ad1[i];
    }
    __syncthreads();

    int n = blockIdx.x * blockDim.x + tid;
    if (n >= NN) return;

    float x[VF];
    #pragma unroll
    for (int k = 0; k < VF; k++) x[k] = feats[(size_t)n * VF + k];

    #pragma unroll
    for (int b = 0; b < 2; b++) {
        float* hout = (b == 0 ? g_h0 : g_h1) + (size_t)n * RS;
        float es[HEADS] = {0.f, 0.f, 0.f};
        float ed[HEADS] = {0.f, 0.f, 0.f};
        #pragma unroll
        for (int j = 0; j < HF; j++) {
            float s = 0.f;
            #pragma unroll
            for (int k = 0; k < VF; k++) s += x[k] * sW[b][k * HF + j];
            hout[j] = s;
            int hh = j >> 4;
            es[hh] += s * sAs[b][j];
            ed[hh] += s * sAd[b][j];
        }
        // log2e folded in: lrelu is positively homogeneous, so
        // exp(lrelu(v)) = ex2(lrelu(v*log2e)) exactly.
        (b == 0 ? g_es4_0 : g_es4_1)[n] =
            make_float4(es[0] * LOG2E, es[1] * LOG2E, es[2] * LOG2E, 0.f);
        (b == 0 ? g_ed4_0 : g_ed4_1)[n] =
            make_float4(ed[0] * LOG2E, ed[1] * LOG2E, ed[2] * LOG2E, 0.f);
    }
}

// ---------------- fill: bucketed CSR build with precomputed p --------------
__device__ __forceinline__ void fill_one(int s, int d,
                                         const float4* __restrict__ es4,
                                         const float4* __restrict__ ed4,
                                         int* __restrict__ cnt,
                                         int4* __restrict__ ent, int cap) {
    float4 a = es4[s];
    float4 b = ed4[d];
    float v0 = a.x + b.x, v1 = a.y + b.y, v2 = a.z + b.z;
    v0 = v0 > 0.f ? v0 : 0.2f * v0;            // leaky_relu(0.2), log2-domain
    v1 = v1 > 0.f ? v1 : 0.2f * v1;
    v2 = v2 > 0.f ? v2 : 0.2f * v2;
    float p0 = ex2(v0), p1 = ex2(v1), p2 = ex2(v2);
    int pos = atomicAdd(&cnt[d], 1);
    if (pos < cap)
        ent[d * cap + pos] = make_int4(__float_as_int(p0), __float_as_int(p1),
                                       __float_as_int(p2), s);
}

__global__ void fill_kernel(const void* __restrict__ e0, const void* __restrict__ e1) {
    int t = blockIdx.x * blockDim.x + threadIdx.x;
    const int H0 = E_INT / 2, H1 = E_NH / 2;
    if (t < H0) {
        int s0, s1, d0, d1;
        if (g_is64[0]) {
            const longlong2* p = (const longlong2*)e0;
            longlong2 sv = p[t], dv = p[H0 + t];
            s0 = (int)sv.x; s1 = (int)sv.y; d0 = (int)dv.x; d1 = (int)dv.y;
        } else {
            const int2* p = (const int2*)e0;
            int2 sv = p[t], dv = p[H0 + t];
            s0 = sv.x; s1 = sv.y; d0 = dv.x; d1 = dv.y;
        }
        fill_one(s0, d0, g_es4_0, g_ed4_0, g_cnt0, g_ent0, CAP0);
        fill_one(s1, d1, g_es4_0, g_ed4_0, g_cnt0, g_ent0, CAP0);
    } else if (t < H0 + H1) {
        int u = t - H0;
        int s0, s1, d0, d1;
        if (g_is64[1]) {
            const longlong2* p = (const longlong2*)e1;
            longlong2 sv = p[u], dv = p[H1 + u];
            s0 = (int)sv.x; s1 = (int)sv.y; d0 = (int)dv.x; d1 = (int)dv.y;
        } else {
            const int2* p = (const int2*)e1;
            int2 sv = p[u], dv = p[H1 + u];
            s0 = sv.x; s1 = sv.y; d0 = dv.x; d1 = dv.y;
        }
        fill_one(s0, d0, g_es4_1, g_ed4_1, g_cnt1, g_ent1, CAP1);
        fill_one(s1, d1, g_es4_1, g_ed4_1, g_cnt1, g_ent1, CAP1);
    }
}

// ---------------- consume: octet per dst row, p from bucket entries --------
__device__ __forceinline__ void edge_acc(int4 E, float4 hA, float4 hB, int sub,
                                         float4& acc0, float4& acc1,
                                         float& d0, float& d1, float& d2) {
    float p0 = __int_as_float(E.x);
    float p1 = __int_as_float(E.y);
    float p2 = __int_as_float(E.z);
    float pa = sub < 4 ? p0 : p1;
    acc0.x += pa * hA.x; acc0.y += pa * hA.y;
    acc0.z += pa * hA.z; acc0.w += pa * hA.w;
    acc1.x += p2 * hB.x; acc1.y += p2 * hB.y;   // lanes 4-7: unused result
    acc1.z += p2 * hB.z; acc1.w += p2 * hB.w;
    d0 += p0; d1 += p1; d2 += p2;
}

__global__ void __launch_bounds__(256, 4) consume_kernel() {
    int t = blockIdx.x * blockDim.x + threadIdx.x;
    int oc = t >> 3, sub = t & 7;
    if (oc >= 2 * NN) return;

    const float* h;
    const int4* ent;
    float* orow;
    int* cntp;
    int cap;
    if (oc < NN) {
        int r = oc;
        h = g_h0; ent = g_ent0 + (size_t)r * CAP0;
        orow = g_out0 + (size_t)r * RS;
        cntp = &g_cnt0[r]; cap = CAP0;
    } else {
        int r = oc - NN;
        h = g_h1; ent = g_ent1 + (size_t)r * CAP1;
        orow = g_out1 + (size_t)r * RS;
        cntp = &g_cnt1[r]; cap = CAP1;
    }
    int deg = *cntp;
    deg = deg < cap ? deg : cap;
    int subm = 8 + (sub & 3);            // head2 slots 8..11 (lanes 4-7 dup)

    float4 acc0 = make_float4(0.f, 0.f, 0.f, 0.f);
    float4 acc1 = make_float4(0.f, 0.f, 0.f, 0.f);
    float d0 = 0.f, d1 = 0.f, d2 = 0.f;

    int i = 0;
    for (; i + 4 <= deg; i += 4) {
        int4 E0 = ent[i], E1 = ent[i + 1], E2 = ent[i + 2], E3 = ent[i + 3];
        const float4* r0 = (const float4*)(h + (size_t)E0.w * RS);
        const float4* r1 = (const float4*)(h + (size_t)E1.w * RS);
        const float4* r2 = (const float4*)(h + (size_t)E2.w * RS);
        const float4* r3 = (const float4*)(h + (size_t)E3.w * RS);
        float4 A0 = r0[sub], B0 = r0[subm];
        float4 A1 = r1[sub], B1 = r1[subm];
        float4 A2 = r2[sub], B2 = r2[subm];
        float4 A3 = r3[sub], B3 = r3[subm];
        edge_acc(E0, A0, B0, sub, acc0, acc1, d0, d1, d2);
        edge_acc(E1, A1, B1, sub, acc0, acc1, d0, d1, d2);
        edge_acc(E2, A2, B2, sub, acc0, acc1, d0, d1, d2);
        edge_acc(E3, A3, B3, sub, acc0, acc1, d0, d1, d2);
    }
    for (; i < deg; i++) {
        int4 E = ent[i];
        const float4* hr = (const float4*)(h + (size_t)E.w * RS);
        float4 hA = hr[sub];
        float4 hB = hr[subm];
        edge_acc(E, hA, hB, sub, acc0, acc1, d0, d1, d2);
    }

    float4* or4 = (float4*)orow;
    or4[sub] = acc0;                                       // heads 0,1
    if (sub < 4) or4[8 + sub] = acc1;                      // head 2
    if (sub == 4) or4[12] = make_float4(d0, d1, d2, 0.f);  // den @ slot 12
    if (sub == 5) *cntp = 0;                               // reset for next replay
}

// ---------------- pooling: octet-per-row, fused normalize + finalize -------
// x_n[d] = raw[n][d] / (den[n][head(d)] + 1e-16)
// out = sum_h ( sum_n e^{tanh(x_n . attw_h)} * (x_n . dw_h) )
//             / ( sum_n e^{tanh(x_n . attw_h)} )  + b
__global__ void __launch_bounds__(256) pool_kernel(
        const float* __restrict__ attw, const float* __restrict__ dw,
        const float* __restrict__ bias, float* __restrict__ out) {
    __shared__ float sA[XDIM * HEADS];   // attw: [96,3] row-major
    __shared__ float sD[XDIM * HEADS];   // dense_w: [288] = [3][96] h-major
    __shared__ float sAcc[6];
    int tid = threadIdx.x;
    for (int i = tid; i < XDIM * HEADS; i += blockDim.x) { sA[i] = attw[i]; sD[i] = dw[i]; }
    if (tid < 6) sAcc[tid] = 0.f;
    __syncthreads();

    int t = blockIdx.x * blockDim.x + tid;
    int n = t >> 3, sub = t & 7;
    unsigned m = 0xFFu << (tid & 24);

    float sh[HEADS] = {0.f, 0.f, 0.f};
    float dh[HEADS] = {0.f, 0.f, 0.f};
    if (n < NN) {
        #pragma unroll
        for (int b = 0; b < 2; b++) {
            const float4* x = (const float4*)((b ? g_out1 : g_out0) + (size_t)n * RS);
            float4 v1 = x[sub];                                      // slots 0..7
            float4 v2 = (sub < 5) ? x[8 + sub]                       // slots 8..12
                                  : make_float4(0.f, 0.f, 0.f, 0.f);
            float dn0 = __shfl_sync(m, v2.x, 4, 8);                  // den @ slot12
            float dn1 = __shfl_sync(m, v2.y, 4, 8);
            float dn2 = __shfl_sync(m, v2.z, 4, 8);
            float inv0 = 1.f / (dn0 + 1e-16f);
            float inv1 = 1.f / (dn1 + 1e-16f);
            float inv2 = 1.f / (dn2 + 1e-16f);
            float invA = (sub < 4) ? inv0 : inv1;
            int base = b * HF;
            float q[4] = {v1.x * invA, v1.y * invA, v1.z * invA, v1.w * invA};
            #pragma unroll
            for (int c = 0; c < 4; c++) {
                int g = base + 4 * sub + c;
                #pragma unroll
                for (int h = 0; h < HEADS; h++) {
                    sh[h] += q[c] * sA[g * HEADS + h];
                    dh[h] += q[c] * sD[h * XDIM + g];
                }
            }
            if (sub < 4) {
                float q2[4] = {v2.x * inv2, v2.y * inv2, v2.z * inv2, v2.w * inv2};
                #pragma unroll
                for (int c = 0; c < 4; c++) {
                    int g = base + 32 + 4 * sub + c;
                    #pragma unroll
                    for (int h = 0; h < HEADS; h++) {
                        sh[h] += q2[c] * sA[g * HEADS + h];
                        dh[h] += q2[c] * sD[h * XDIM + g];
                    }
                }
            }
        }
    }
    // octet reduce (width 8) -> octet lane 0 has this node's sh/dh
    #pragma unroll
    for (int off = 4; off > 0; off >>= 1) {
        #pragma unroll
        for (int h = 0; h < HEADS; h++) {
            sh[h] += __shfl_down_sync(0xFFFFFFFFu, sh[h], off, 8);
            dh[h] += __shfl_down_sync(0xFFFFFFFFu, dh[h], off, 8);
        }
    }
    float num[HEADS] = {0.f, 0.f, 0.f};
    float den[HEADS] = {0.f, 0.f, 0.f};
    if (sub == 0 && n < NN) {
        #pragma unroll
        for (int h = 0; h < HEADS; h++) {
            float w = __expf(tanhf(sh[h]));
            num[h] = w * dh[h];
            den[h] = w;
        }
    }
    // cross-octet reduce (valid values at lanes 0,8,16,24; others zero)
    #pragma unroll
    for (int h = 0; h < HEADS; h++) {
        num[h] += __shfl_down_sync(0xFFFFFFFFu, num[h], 16);
        den[h] += __shfl_down_sync(0xFFFFFFFFu, den[h], 16);
        num[h] += __shfl_down_sync(0xFFFFFFFFu, num[h], 8);
        den[h] += __shfl_down_sync(0xFFFFFFFFu, den[h], 8);
    }
    if ((tid & 31) == 0) {
        #pragma unroll
        for (int h = 0; h < HEADS; h++) {
            atomicAdd(&sAcc[h], num[h]);
            atomicAdd(&sAcc[HEADS + h], den[h]);
        }
    }
    __syncthreads();
    if (tid < 6) atomicAdd(&g_acc[tid], sAcc[tid]);
    __threadfence();
    __syncthreads();
    if (tid == 0) {
        int done = atomicAdd(&g_done, 1);
        if (done == (int)gridDim.x - 1) {          // last block finalizes
            __threadfence();
            float r = 0.f;
            #pragma unroll
            for (int h = 0; h < HEADS; h++) r += g_acc[h] / g_acc[HEADS + h];
            out[0] = r + bias[0];
            #pragma unroll
            for (int k = 0; k < 6; k++) g_acc[k] = 0.f;   // reset for replay
            g_done = 0;
        }
    }
}

// ---------------------------------------------------------------------------
extern "C" void kernel_launch(void* const* d_in, const int* in_sizes, int n_in,
                              void* d_out, int out_size) {
    const float* node_feats = (const float*)d_in[0];
    const float* W_int   = (const float*)d_in[1];
    const float* asrc_i  = (const float*)d_in[2];
    const float* adst_i  = (const float*)d_in[3];
    const float* W_nh    = (const float*)d_in[4];
    const float* asrc_n  = (const float*)d_in[5];
    const float* adst_n  = (const float*)d_in[6];
    const float* att_w   = (const float*)d_in[7];
    const float* dense_w = (const float*)d_in[8];
    const float* dense_b = (const float*)d_in[9];
    const void*  edge_i  = d_in[10];
    const void*  edge_n  = d_in[11];
    float* out = (float*)d_out;

    node_kernel<<<(NN + 255) / 256, 256>>>(node_feats, W_int, asrc_i, adst_i,
                                           W_nh, asrc_n, adst_n, edge_i, edge_n);
    fill_kernel<<<((E_INT + E_NH) / 2 + 255) / 256, 256>>>(edge_i, edge_n);
    consume_kernel<<<(2 * NN * 8 + 255) / 256, 256>>>();
    pool_kernel<<<(NN * 8 + 255) / 256, 256>>>(att_w, dense_w, dense_b, out);
}